// round 5
// baseline (speedup 1.0000x reference)
#include <cuda_runtime.h>
#include <math_constants.h>

// queries/keys/values: 8192 fp32 each; 8 segments of 1024 contiguous floats.
// dists[i][j] = exact DTW(|a-b|) between q-seg i and k-seg j (1024x1024 DP).
// A = softmax(0.5*dists, axis=-1); out = A @ value-segments.

#define N_SEG    8
#define SEG_LEN  1024
#define C_COLS   8                            // columns per thread
#define R_ROWS   4                            // rows per pipeline step
#define P_THR    128
#define N_BLK    (SEG_LEN / R_ROWS)           // 256 row-blocks
#define SKEW_W   8                            // extra skew per warp seam
#define SIG_MAX  (P_THR - 1 + SKEW_W * 3)     // 151
#define N_STEPS  (N_BLK + SIG_MAX)            // 407
#define SUPER    8                            // steps per __syncthreads
#define NSUPER   ((N_STEPS + SUPER - 1) / SUPER)  // 51 -> 408 executed steps
#define RING     16

__device__ float        g_dists[N_SEG * N_SEG];
__device__ unsigned int g_count = 0;          // self-resetting via atomicInc wrap

// One CTA per (qi,kj). Branch-free pipelined 4x8 register-tile DTW with the
// tile emitted in ANTI-DIAGONAL order (11 diagonals of <=4 independent cells)
// so the serial min-add chain is 11*8 cyc instead of 4*64 -> issue-bound.
// Thread t owns cols [8t,8t+8); skew sigma = t + 8*warp; step s -> block
// b = s - sigma. INF is a fixed point of the recurrence, so out-of-range
// threads run the same code on INF state and produce exactly the correct
// virtual boundaries. Intra-warp handoff: shfl_up. Warp seams: 16-slot smem
// ring, consumer prefetches slot s-8 (slack 9 > SUPER=8 guarantees exactly
// one barrier between producer store and consumer load).
__global__ __launch_bounds__(P_THR, 1)
void dtw_kernel(const float* __restrict__ q, const float* __restrict__ k,
                const float* __restrict__ values, float* __restrict__ out_g) {
    const int qi = blockIdx.x;
    const int kj = blockIdx.y;
    const float* __restrict__ xrow = q + qi * SEG_LEN;
    const float* __restrict__ ycol = k + kj * SEG_LEN;

    __shared__ float  sx[SEG_LEN];
    __shared__ float4 ring[3][RING];           // [seam][slot] (4 boundary vals)
    __shared__ float  sA[N_SEG][N_SEG];
    __shared__ unsigned s_last;

    const int t    = threadIdx.x;
    const int lane = t & 31;
    const int warp = t >> 5;
    const int sigma = t + SKEW_W * warp;
    const float INF = CUDART_INF_F;

    for (int i = t; i < SEG_LEN / 4; i += P_THR)
        reinterpret_cast<float4*>(sx)[i] = reinterpret_cast<const float4*>(xrow)[i];
    {
        const float4 inf4 = make_float4(INF, INF, INF, INF);
        float4* rp = &ring[0][0];
        for (int i = t; i < 3 * RING; i += P_THR) rp[i] = inf4;
    }

    float y[C_COLS];
    {
        const float4* y4 = reinterpret_cast<const float4*>(ycol + t * C_COLS);
        float4 a = y4[0], b = y4[1];
        y[0]=a.x; y[1]=a.y; y[2]=a.z; y[3]=a.w;
        y[4]=b.x; y[5]=b.y; y[6]=b.z; y[7]=b.w;
    }

    float U[C_COLS];                 // d[r-1, base+j] (rolling previous row)
    float S[C_COLS];                 // saved up-left values (old U)
    float lv[R_ROWS];                // incoming left boundary for this block
    float ov[R_ROWS];                // outgoing right boundary of this block
#pragma unroll
    for (int j = 0; j < C_COLS; j++) { U[j] = INF; S[j] = INF; }
#pragma unroll
    for (int r = 0; r < R_ROWS; r++) { lv[r] = INF; ov[r] = INF; }
    float carry = (t == 0) ? 0.0f : INF;   // d[r0-1, base-1] entering a block
    float res = 0.0f;

    __syncthreads();

    float xr[R_ROWS];
    {   // preload x rows for step 0 (b = -sigma clamps to block 0)
        const float4 a = reinterpret_cast<const float4*>(sx)[0];
        xr[0]=a.x; xr[1]=a.y; xr[2]=a.z; xr[3]=a.w;
    }

    int s = 0;
    for (int sup = 0; sup < NSUPER; sup++) {
#pragma unroll
        for (int u = 0; u < SUPER; u++, s++) {
            const int b = s - sigma;

            float L[R_ROWS];             // running left value per row
#pragma unroll
            for (int r = 0; r < R_ROWS; r++) L[r] = lv[r];

            // 4x8 tile in anti-diagonal order: cells on a diagonal are
            // independent -> chain length = 11 diagonals, not 4 serial rows.
#pragma unroll
            for (int dg = 0; dg < R_ROWS + C_COLS - 1; dg++) {
#pragma unroll
                for (int rr = 0; rr < R_ROWS; rr++) {
                    const int j = dg - rr;
                    if (0 <= j && j < C_COLS) {
                        const float ul = (j == 0)
                                       ? ((rr == 0) ? carry : lv[rr - 1])
                                       : S[j - 1];
                        const float oldU = U[j];
                        const float a = fminf(oldU, ul);
                        const float dd = fabsf(xr[rr] - y[j]) + fminf(a, L[rr]);
                        S[j] = oldU;
                        U[j] = dd;
                        L[rr] = dd;
                    }
                }
            }
#pragma unroll
            for (int r = 0; r < R_ROWS; r++) ov[r] = L[r];

            res = (b == N_BLK - 1) ? ov[3] : res;   // d[1023, base+7]
            carry = lv[3];

            // intra-warp handoff for next step (neighbor's block b+1 == ours this step)
            lv[0] = __shfl_up_sync(0xffffffffu, ov[0], 1);
            lv[1] = __shfl_up_sync(0xffffffffu, ov[1], 1);
            lv[2] = __shfl_up_sync(0xffffffffu, ov[2], 1);
            lv[3] = __shfl_up_sync(0xffffffffu, ov[3], 1);

            if (lane == 31 && warp < 3)             // seam producer
                ring[warp][s & (RING - 1)] = make_float4(ov[0], ov[1], ov[2], ov[3]);

            if (lane == 0) {                        // seam consumer (for step s+1)
                if (warp != 0) {
                    const float4 a = ring[warp - 1][(s - SKEW_W) & (RING - 1)];
                    lv[0]=a.x; lv[1]=a.y; lv[2]=a.z; lv[3]=a.w;
                } else {
                    lv[0]=INF; lv[1]=INF; lv[2]=INF; lv[3]=INF;
                }
            }

            // prefetch x rows for next step (clamped; garbage is harmless)
            const int bn = s + 1 - sigma;
            const int i4 = min(max(bn, 0), N_BLK - 1);
            const float4 xa = reinterpret_cast<const float4*>(sx)[i4];
            xr[0]=xa.x; xr[1]=xa.y; xr[2]=xa.z; xr[3]=xa.w;
        }
        __syncthreads();
    }

    if (t == P_THR - 1) g_dists[qi * N_SEG + kj] = res;

    // ---- fused epilogue: last CTA to arrive does softmax + A @ V ----
    __threadfence();
    if (t == 0) s_last = atomicInc(&g_count, N_SEG * N_SEG - 1);
    __syncthreads();
    if (s_last != N_SEG * N_SEG - 1) return;
    __threadfence();

    if (t < N_SEG) {
        float l[N_SEG];
        float m = -INF;
#pragma unroll
        for (int j = 0; j < N_SEG; j++) {
            l[j] = 0.5f * g_dists[t * N_SEG + j];   // scale = 1/sqrt(4)
            m = fmaxf(m, l[j]);
        }
        float ssum = 0.0f;
#pragma unroll
        for (int j = 0; j < N_SEG; j++) {
            l[j] = expf(l[j] - m);
            ssum += l[j];
        }
        const float inv = 1.0f / ssum;
#pragma unroll
        for (int j = 0; j < N_SEG; j++) sA[t][j] = l[j] * inv;
    }
    __syncthreads();

    const float4* v4 = reinterpret_cast<const float4*>(values);
    float4* o4 = reinterpret_cast<float4*>(out_g);
#pragma unroll
    for (int n = 0; n < 16; n++) {
        const int g = t + n * P_THR;                // float4 index (2048 total)
        const int i = g >> 8;                       // segment (256 float4/seg)
        const int c = g & 255;
        float4 acc = make_float4(0.f, 0.f, 0.f, 0.f);
#pragma unroll
        for (int j = 0; j < N_SEG; j++) {
            const float w = sA[i][j];
            const float4 v = v4[j * 256 + c];
            acc.x += w * v.x;
            acc.y += w * v.y;
            acc.z += w * v.z;
            acc.w += w * v.w;
        }
        o4[g] = acc;
    }
}

extern "C" void kernel_launch(void* const* d_in, const int* in_sizes, int n_in,
                              void* d_out, int out_size) {
    const float* queries = (const float*)d_in[0];
    const float* keys    = (const float*)d_in[1];
    const float* values  = (const float*)d_in[2];
    float* out = (float*)d_out;

    dim3 grid(N_SEG, N_SEG);
    dtw_kernel<<<grid, P_THR>>>(queries, keys, values, out);
}